// round 9
// baseline (speedup 1.0000x reference)
#include <cuda_runtime.h>
#include <cuda_bf16.h>
#include <math.h>
#include <stdint.h>

// Problem shape (fixed): B=4, T=2048, C=1024, fp32 in/out.
#define BATCH 4
#define SEQ   2048
#define CH    1024
#define MTOT  (BATCH*SEQ)          // 8192
#define PELEM (BATCH*SEQ*SEQ)      // 16777216

typedef __nv_bfloat16 bf16;

// ---------------------------------------------------------------------------
// Device-global scratch
// ---------------------------------------------------------------------------
__device__ __align__(128) bf16 g_XH[MTOT*CH],  g_XL[MTOT*CH];
__device__ __align__(128) bf16 g_WQH[CH*CH],   g_WQL[CH*CH];
__device__ __align__(128) bf16 g_WKH[CH*CH],   g_WKL[CH*CH];
__device__ __align__(128) bf16 g_WVH[CH*CH],   g_WVL[CH*CH];
__device__ __align__(128) bf16 g_WOH[CH*CH],   g_WOL[CH*CH];
__device__ __align__(128) bf16 g_QH[MTOT*CH],  g_QL[MTOT*CH];
__device__ __align__(128) bf16 g_KH[MTOT*CH],  g_KL[MTOT*CH];
__device__ __align__(128) bf16 g_VTH[MTOT*CH], g_VTL[MTOT*CH];  // V^T [b][c][t]
__device__ __align__(128) bf16 g_OH[MTOT*CH],  g_OL[MTOT*CH];
__device__ __align__(128) bf16 g_PH[PELEM],    g_PL[PELEM];     // exp(S) hi/lo
__device__ __align__(128) float g_L[MTOT];                      // row sums of exp
__device__ __align__(128) float2 g_ROPE[SEQ*(CH/2)];            // cos/sin table

#define TB_XH  0
#define TB_WQH 2
#define TB_WKH 4
#define TB_WVH 6
#define TB_WOH 8
#define TB_QH  10
#define TB_KH  12
#define TB_VTH 14
#define TB_OH  16
#define TB_PH  18

__device__ __forceinline__ bf16* bbuf(int tag) {
    switch (tag) {
        case TB_XH:      return g_XH;  case TB_XH + 1:  return g_XL;
        case TB_WQH:     return g_WQH; case TB_WQH + 1: return g_WQL;
        case TB_WKH:     return g_WKH; case TB_WKH + 1: return g_WKL;
        case TB_WVH:     return g_WVH; case TB_WVH + 1: return g_WVL;
        case TB_WOH:     return g_WOH; case TB_WOH + 1: return g_WOL;
        case TB_QH:      return g_QH;  case TB_QH + 1:  return g_QL;
        case TB_KH:      return g_KH;  case TB_KH + 1:  return g_KL;
        case TB_VTH:     return g_VTH; case TB_VTH + 1: return g_VTL;
        case TB_OH:      return g_OH;  case TB_OH + 1:  return g_OL;
        case TB_PH:      return g_PH;  case TB_PH + 1:  return g_PL;
        default:         return g_XH;
    }
}

// ---------------------------------------------------------------------------
// PTX helpers (arch-agnostic at plain sm_100)
// ---------------------------------------------------------------------------
__device__ __forceinline__ uint32_t s2u(const void* p) {
    uint32_t a;
    asm("{ .reg .u64 t; cvta.to.shared.u64 t, %1; cvt.u32.u64 %0, t; }" : "=r"(a) : "l"(p));
    return a;
}
__device__ __forceinline__ void cp16(uint32_t dst, const void* src) {
    asm volatile("cp.async.cg.shared.global [%0], [%1], 16;" :: "r"(dst), "l"(src) : "memory");
}
__device__ __forceinline__ void cp_commit() {
    asm volatile("cp.async.commit_group;" ::: "memory");
}
__device__ __forceinline__ void ldsm4(uint32_t& r0, uint32_t& r1, uint32_t& r2, uint32_t& r3,
                                      uint32_t addr) {
    asm volatile("ldmatrix.sync.aligned.m8n8.x4.shared.b16 {%0,%1,%2,%3}, [%4];"
                 : "=r"(r0), "=r"(r1), "=r"(r2), "=r"(r3) : "r"(addr));
}
__device__ __forceinline__ void mma16816(float* c, const uint32_t* a, const uint32_t* b) {
    asm volatile(
        "mma.sync.aligned.m16n8k16.row.col.f32.bf16.bf16.f32 "
        "{%0,%1,%2,%3}, {%4,%5,%6,%7}, {%8,%9}, {%0,%1,%2,%3};"
        : "+f"(c[0]), "+f"(c[1]), "+f"(c[2]), "+f"(c[3])
        : "r"(a[0]), "r"(a[1]), "r"(a[2]), "r"(a[3]), "r"(b[0]), "r"(b[1]));
}
__device__ __forceinline__ void split2(float v, bf16& h, bf16& l) {
    h = __float2bfloat16(v);
    l = __float2bfloat16(v - __bfloat162float(h));
}
__device__ __forceinline__ uint32_t pack2(bf16 a, bf16 b) {
    uint16_t x = *(uint16_t*)&a, y = *(uint16_t*)&b;
    return (uint32_t)x | ((uint32_t)y << 16);
}

// ---------------------------------------------------------------------------
// Swizzled smem layout: tile = 128 rows x 32 bf16 (64B/row), no padding.
// ---------------------------------------------------------------------------
__device__ __forceinline__ uint32_t swz(uint32_t row, uint32_t kseg) {
    return row * 64u + ((kseg ^ ((row >> 1) & 3u)) * 16u);
}

#define NSTG    3
#define TILE_B  8192                     // 128*64B
#define STAGE_B (4*TILE_B)               // Ah,Al,Bh,Bl = 32768
#define SMEM_TOT (NSTG*STAGE_B)          // 98304

// ---------------------------------------------------------------------------
// Mainloop: acc += A[M,K] @ B[N,K]^T, hi/lo split (Ah·Bl -> Ah·Bh -> Al·Bh),
// tile 128x128, BK=32, 8 warps, 3-stage cp.async, single sync per chunk.
// Fragment schedule: af,bt (pass-1 ops) first, bh behind them; al hoisted
// before pass-2 MMAs so pass 3 opens stall-free; next-chunk cp.async split
// into two halves issued inside the compute.
// ---------------------------------------------------------------------------
template <bool KLIM>
__device__ __forceinline__ void hmma_mainloop(
    float (&acc)[2][8][4],
    const bf16* __restrict__ Ah, const bf16* __restrict__ Al,
    const bf16* __restrict__ Bh, const bf16* __restrict__ Bl,
    int ldA, int ldB, int bm, int bn, int Ktot, uint32_t sb) {

    const int tid = threadIdx.x;
    const int wid = tid >> 5, lane = tid & 31;
    const int wm = wid & 3, wn = wid >> 2;

    const int lrow = tid >> 1;
    const int k2   = (tid & 1) * 2;
    const uint32_t s0 = swz(lrow, k2);
    const uint32_t s1 = swz(lrow, k2 + 1);
    const long long aRow = (long long)(bm * 128 + lrow) * ldA + k2 * 8;
    const long long bRow = (long long)(bn * 128 + lrow) * ldB + k2 * 8;

    const int Kend = KLIM ? min(Ktot, (bm + 1) * 128) : Ktot;
    const int nch  = Kend >> 5;

    auto issueA = [&](int kt, int stage) {     // A hi/lo halves (4 cp)
        const uint32_t d = sb + (uint32_t)stage * STAGE_B;
        const long long g = (long long)kt * 32;
        const bf16* pah = Ah + aRow + g;
        const bf16* pal = Al + aRow + g;
        cp16(d + s0,          pah);  cp16(d + s1,          pah + 8);
        cp16(d + TILE_B + s0, pal);  cp16(d + TILE_B + s1, pal + 8);
    };
    auto issueB = [&](int kt, int stage) {     // B hi/lo halves (4 cp) + commit
        const uint32_t d = sb + (uint32_t)stage * STAGE_B;
        const long long g = (long long)kt * 32;
        const bf16* pbh = Bh + bRow + g;
        const bf16* pbl = Bl + bRow + g;
        cp16(d + 2 * TILE_B + s0, pbh);  cp16(d + 2 * TILE_B + s1, pbh + 8);
        cp16(d + 3 * TILE_B + s0, pbl);  cp16(d + 3 * TILE_B + s1, pbl + 8);
        cp_commit();
    };

    const int la_row = (lane & 7) + ((lane >> 3) & 1) * 8;
    const int la_ks  = (lane >> 4) & 1;
    const int lb_row = (lane & 7) + ((lane >> 4) & 1) * 8;
    const int lb_ks  = (lane >> 3) & 1;

    issueA(0, 0); issueB(0, 0);
    if (1 < nch) { issueA(1, 1); issueB(1, 1); }

    int st = 0;
    for (int kt = 0; kt < nch; kt++) {
        if (kt + 1 < nch) {
            asm volatile("cp.async.wait_group 1;" ::: "memory");
        } else {
            asm volatile("cp.async.wait_group 0;" ::: "memory");
        }
        __syncthreads();

        const bool pre = (kt + 2 < nch);
        const int  st2 = (st + 2 >= NSTG) ? st + 2 - NSTG : st + 2;

        const uint32_t aHi = sb + (uint32_t)st * STAGE_B;
        const uint32_t aLo = aHi + TILE_B;
        const uint32_t bHi = aHi + 2 * TILE_B;
        const uint32_t bLo = aHi + 3 * TILE_B;

#pragma unroll
        for (int ks = 0; ks < 2; ks++) {
            const uint32_t ka = (uint32_t)(ks * 2 + la_ks);
            const uint32_t kb = (uint32_t)(ks * 2 + lb_ks);

            // ---- pass-1 operands first (af, bt), pass-2's bh behind ----
            uint32_t af[2][4];
#pragma unroll
            for (int i = 0; i < 2; i++)
                ldsm4(af[i][0], af[i][1], af[i][2], af[i][3],
                      aHi + swz((uint32_t)(wm * 32 + i * 16 + la_row), ka));
            uint32_t bt[4][4];
#pragma unroll
            for (int p = 0; p < 4; p++)
                ldsm4(bt[p][0], bt[p][1], bt[p][2], bt[p][3],
                      bLo + swz((uint32_t)(wn * 64 + p * 16 + lb_row), kb));
            uint32_t bh[4][4];
#pragma unroll
            for (int p = 0; p < 4; p++)
                ldsm4(bh[p][0], bh[p][1], bh[p][2], bh[p][3],
                      bHi + swz((uint32_t)(wn * 64 + p * 16 + lb_row), kb));

            // pass 1: Ah x Bl
#pragma unroll
            for (int i = 0; i < 2; i++)
#pragma unroll
                for (int p = 0; p < 4; p++) {
                    mma16816(acc[i][p * 2 + 0], af[i], &bt[p][0]);
                    mma16816(acc[i][p * 2 + 1], af[i], &bt[p][2]);
                }

            // spread the next-chunk cp.async between passes
            if (pre) { if (ks == 0) issueA(kt + 2, st2); else issueB(kt + 2, st2); }

            // pass-3 operands issued here: pass-2's 16 MMAs cover the latency
            uint32_t al[2][4];
#pragma unroll
            for (int i = 0; i < 2; i++)
                ldsm4(al[i][0], al[i][1], al[i][2], al[i][3],
                      aLo + swz((uint32_t)(wm * 32 + i * 16 + la_row), ka));

            // pass 2: Ah x Bh
#pragma unroll
            for (int i = 0; i < 2; i++)
#pragma unroll
                for (int p = 0; p < 4; p++) {
                    mma16816(acc[i][p * 2 + 0], af[i], &bh[p][0]);
                    mma16816(acc[i][p * 2 + 1], af[i], &bh[p][2]);
                }

            // pass 3: Al x Bh
#pragma unroll
            for (int i = 0; i < 2; i++)
#pragma unroll
                for (int p = 0; p < 4; p++) {
                    mma16816(acc[i][p * 2 + 0], al[i], &bh[p][0]);
                    mma16816(acc[i][p * 2 + 1], al[i], &bh[p][2]);
                }
        }
        st = (st + 1 == NSTG) ? 0 : st + 1;
    }
}

// ---------------------------------------------------------------------------
// Fused QKV projection: z = 0/1/2 -> (Wq,RoPE->Q), (Wk,RoPE->K), (Wv->V^T)
// ---------------------------------------------------------------------------
__global__ void __launch_bounds__(256, 2)
qkv_kernel(const float* __restrict__ bq, const float* __restrict__ bk,
           const float* __restrict__ bv) {
    const int bm = blockIdx.y, bn = blockIdx.x, z = blockIdx.z;

    extern __shared__ char smem[];
    const uint32_t sb = s2u(smem);
    const int tid = threadIdx.x, wid = tid >> 5, lane = tid & 31;
    const int wm = wid & 3, wn = wid >> 2;

    const int wtag = TB_WQH + 2 * z;
    const float* bias = (z == 0) ? bq : (z == 1) ? bk : bv;

    float acc[2][8][4];
#pragma unroll
    for (int i = 0; i < 2; i++)
#pragma unroll
        for (int j = 0; j < 8; j++)
#pragma unroll
            for (int q = 0; q < 4; q++) acc[i][j][q] = 0.0f;

    hmma_mainloop<false>(acc, g_XH, g_XL, bbuf(wtag), bbuf(wtag + 1),
                         CH, CH, bm, bn, CH, sb);

    const int rbase = bm * 128 + wm * 32 + (lane >> 2);
    const int cbase = bn * 128 + wn * 64 + (lane & 3) * 2;
#pragma unroll
    for (int i = 0; i < 2; i++) {
#pragma unroll
        for (int h = 0; h < 2; h++) {
            const int r = rbase + i * 16 + h * 8;
            const int t = r & (SEQ - 1);
            const float2* tab = g_ROPE + (long long)t * (CH / 2);
#pragma unroll
            for (int j = 0; j < 8; j++) {
                const int c = cbase + j * 8;
                float v0 = acc[i][j][h * 2 + 0] + bias[c];
                float v1 = acc[i][j][h * 2 + 1] + bias[c + 1];
                if (z < 2) {
                    float2 cs = tab[c >> 1];
                    float e = v0, o = v1;
                    v0 = e * cs.x - o * cs.y;
                    v1 = o * cs.x + e * cs.y;
                    bf16 h0, l0, h1, l1;
                    split2(v0, h0, l0);
                    split2(v1, h1, l1);
                    bf16* H = (z == 0) ? g_QH : g_KH;
                    bf16* L = (z == 0) ? g_QL : g_KL;
                    const long long idx = (long long)r * CH + c;
                    *(uint32_t*)(H + idx) = pack2(h0, h1);
                    *(uint32_t*)(L + idx) = pack2(l0, l1);
                } else {
                    const int b = r >> 11, tq = r & (SEQ - 1);
                    bf16 h0, l0, h1, l1;
                    split2(v0, h0, l0);
                    split2(v1, h1, l1);
                    const long long i0 = ((long long)b * CH + c) * SEQ + tq;
                    const long long i1 = ((long long)b * CH + c + 1) * SEQ + tq;
                    g_VTH[i0] = h0; g_VTL[i0] = l0;
                    g_VTH[i1] = h1; g_VTL[i1] = l1;
                }
            }
        }
    }
}

// ---------------------------------------------------------------------------
// Generic GEMM.
//   OUT_MODE: 0 = fp32 to cext (+bias)                 [out projection]
//             1 = bf16 hi/lo to tagOut (LSCALE: /g_L)  [P·V -> O]
//             2 = exp(S*alpha) causal-masked -> PH/PL hi/lo + row-sum atomics
//   CAUSAL:   1D triangular grid decode; REV: reverse bm (LPT for PV)
// ---------------------------------------------------------------------------
template <int OUT_MODE, bool BIAS, bool CAUSAL, bool KLIM, bool REV, bool LSCALE>
__global__ void __launch_bounds__(256, 2)
hmma_gemm(int tagA, int tagB, int ldA, int ldB, long long sA, long long sB,
          const float* __restrict__ bias, float* __restrict__ cext,
          int ldC, long long sC, int tagOut, int Ktot, float alpha) {
    int bm, bn;
    if (CAUSAL) {
        const int x = blockIdx.x;
        int r = (int)((sqrtf(8.0f * x + 1.0f) - 1.0f) * 0.5f);
        while ((r + 1) * (r + 2) / 2 <= x) r++;
        while (r * (r + 1) / 2 > x) r--;
        bm = r;
        bn = x - r * (r + 1) / 2;
    } else {
        bm = REV ? (int)(gridDim.y - 1 - blockIdx.y) : (int)blockIdx.y;
        bn = blockIdx.x;
    }
    const int z = blockIdx.z;

    extern __shared__ char smem[];
    const uint32_t sb = s2u(smem);
    const int tid = threadIdx.x, wid = tid >> 5, lane = tid & 31;
    const int wm = wid & 3, wn = wid >> 2;

    const bf16* Ah = bbuf(tagA)     + (long long)z * sA;
    const bf16* Al = bbuf(tagA + 1) + (long long)z * sA;
    const bf16* Bh = bbuf(tagB)     + (long long)z * sB;
    const bf16* Bl = bbuf(tagB + 1) + (long long)z * sB;

    float acc[2][8][4];
#pragma unroll
    for (int i = 0; i < 2; i++)
#pragma unroll
        for (int j = 0; j < 8; j++)
#pragma unroll
            for (int q = 0; q < 4; q++) acc[i][j][q] = 0.0f;

    hmma_mainloop<KLIM>(acc, Ah, Al, Bh, Bl, ldA, ldB, bm, bn, Ktot, sb);

    const int rbase = bm * 128 + wm * 32 + (lane >> 2);
    const int cbase = bn * 128 + wn * 64 + (lane & 3) * 2;

    if (OUT_MODE == 2) {
        // e = (c<=r) ? exp(S*alpha) : 0 -> PH/PL hi/lo; atomic row sums -> g_L
        bf16* PH = g_PH + (long long)z * sC;
        bf16* PL = g_PL + (long long)z * sC;
        float rsum[2][2];
        rsum[0][0] = rsum[0][1] = rsum[1][0] = rsum[1][1] = 0.0f;
#pragma unroll
        for (int i = 0; i < 2; i++) {
#pragma unroll
            for (int h = 0; h < 2; h++) {
                const int r = rbase + i * 16 + h * 8;
#pragma unroll
                for (int j = 0; j < 8; j++) {
                    const int c = cbase + j * 8;
                    float e0 = (c     <= r) ? __expf(acc[i][j][h * 2 + 0] * alpha) : 0.0f;
                    float e1 = (c + 1 <= r) ? __expf(acc[i][j][h * 2 + 1] * alpha) : 0.0f;
                    bf16 h0, l0, h1, l1;
                    split2(e0, h0, l0);
                    split2(e1, h1, l1);
                    const long long idx = (long long)r * ldC + c;
                    *(uint32_t*)(PH + idx) = pack2(h0, h1);
                    *(uint32_t*)(PL + idx) = pack2(l0, l1);
                    rsum[i][h] += e0 + e1;
                }
            }
        }
#pragma unroll
        for (int i = 0; i < 2; i++)
#pragma unroll
            for (int h = 0; h < 2; h++) {
                float s = rsum[i][h];
                s += __shfl_xor_sync(0xffffffffu, s, 1);
                s += __shfl_xor_sync(0xffffffffu, s, 2);
                if ((lane & 3) == 0)
                    atomicAdd(&g_L[z * SEQ + rbase + i * 16 + h * 8], s);
            }
        return;
    }

#pragma unroll
    for (int i = 0; i < 2; i++) {
#pragma unroll
        for (int h = 0; h < 2; h++) {
            const int r = rbase + i * 16 + h * 8;
            const float linv = LSCALE ? (1.0f / g_L[z * SEQ + r]) : 1.0f;
#pragma unroll
            for (int j = 0; j < 8; j++) {
                const int c = cbase + j * 8;
                float v0 = acc[i][j][h * 2 + 0] * alpha;
                float v1 = acc[i][j][h * 2 + 1] * alpha;
                if (LSCALE) { v0 *= linv; v1 *= linv; }
                if (BIAS) { v0 += bias[c]; v1 += bias[c + 1]; }
                if (OUT_MODE == 0) {
                    float* C = cext + (long long)z * sC;
                    *(float2*)(C + (long long)r * ldC + c) = make_float2(v0, v1);
                } else {
                    bf16 h0, l0, h1, l1;
                    split2(v0, h0, l0);
                    split2(v1, h1, l1);
                    bf16* H = bbuf(tagOut)     + (long long)z * sC;
                    bf16* L = bbuf(tagOut + 1) + (long long)z * sC;
                    const long long idx = (long long)r * ldC + c;
                    *(uint32_t*)(H + idx) = pack2(h0, h1);
                    *(uint32_t*)(L + idx) = pack2(l0, l1);
                }
            }
        }
    }
}

// ---------------------------------------------------------------------------
// RoPE table (reference-matching fp32 pipeline)
// ---------------------------------------------------------------------------
__global__ void rope_table_kernel() {
    int idx = blockIdx.x * blockDim.x + threadIdx.x;
    const int half = CH >> 1;
    if (idx >= SEQ * half) return;
    int t = idx / half, p = idx - t * half;
    float inv = 1.0f / powf(10000.0f, (float)(2 * p) / (float)CH);
    float s, c;
    sincosf((float)t * inv, &s, &c);
    g_ROPE[idx] = make_float2(c, s);
}

// zero g_L each launch (graph replays)
__global__ void zero_l_kernel() {
    int i = blockIdx.x * blockDim.x + threadIdx.x;
    if (i < MTOT) g_L[i] = 0.0f;
}

// fp32 -> bf16 hi/lo split (vectorized)
__global__ void split_kernel(const float* __restrict__ src, int tagHi, int n4) {
    int i = blockIdx.x * blockDim.x + threadIdx.x;
    if (i >= n4) return;
    float4 x = ((const float4*)src)[i];
    bf16 h[4], l[4];
    split2(x.x, h[0], l[0]); split2(x.y, h[1], l[1]);
    split2(x.z, h[2], l[2]); split2(x.w, h[3], l[3]);
    *(uint2*)(bbuf(tagHi)     + (long long)i * 4) = *(const uint2*)h;
    *(uint2*)(bbuf(tagHi + 1) + (long long)i * 4) = *(const uint2*)l;
}

// W [K,N] -> W^T hi/lo [N,K]; z selects the weight
__global__ void wT_split_kernel(const float* __restrict__ W0, const float* __restrict__ W1,
                                const float* __restrict__ W2, const float* __restrict__ W3) {
    __shared__ float tile[32][33];
    const int z = blockIdx.z;
    const float* W = (z == 0) ? W0 : (z == 1) ? W1 : (z == 2) ? W2 : W3;
    const int tagHi = TB_WQH + 2 * z;
    const int n0 = blockIdx.x * 32, k0 = blockIdx.y * 32;
    const int tx = threadIdx.x, ty = threadIdx.y;   // 32 x 8
#pragma unroll
    for (int i = 0; i < 32; i += 8)
        tile[ty + i][tx] = W[(long long)(k0 + ty + i) * CH + n0 + tx];
    __syncthreads();
    bf16* H = bbuf(tagHi);
    bf16* L = bbuf(tagHi + 1);
#pragma unroll
    for (int i = 0; i < 32; i += 8) {
        bf16 h, l;
        split2(tile[tx][ty + i], h, l);
        const long long idx = (long long)(n0 + ty + i) * CH + k0 + tx;
        H[idx] = h;
        L[idx] = l;
    }
}

// ---------------------------------------------------------------------------
// Launch
// ---------------------------------------------------------------------------
extern "C" void kernel_launch(void* const* d_in, const int* in_sizes, int n_in,
                              void* d_out, int out_size) {
    const float* x  = (const float*)d_in[0];
    const float* Wq = (const float*)d_in[1];
    const float* bq = (const float*)d_in[2];
    const float* Wk = (const float*)d_in[3];
    const float* bk = (const float*)d_in[4];
    const float* Wv = (const float*)d_in[5];
    const float* bv = (const float*)d_in[6];
    const float* Wo = (const float*)d_in[7];
    const float* bo = (const float*)d_in[8];
    float* out = (float*)d_out;

    const long long TC = (long long)SEQ * CH;
    const long long TT = (long long)SEQ * SEQ;

    cudaFuncSetAttribute(qkv_kernel,
                         cudaFuncAttributeMaxDynamicSharedMemorySize, SMEM_TOT);
    cudaFuncSetAttribute(hmma_gemm<2, false, true,  false, false, false>,
                         cudaFuncAttributeMaxDynamicSharedMemorySize, SMEM_TOT);
    cudaFuncSetAttribute(hmma_gemm<1, false, false, true,  true,  true>,
                         cudaFuncAttributeMaxDynamicSharedMemorySize, SMEM_TOT);
    cudaFuncSetAttribute(hmma_gemm<0, true,  false, false, false, false>,
                         cudaFuncAttributeMaxDynamicSharedMemorySize, SMEM_TOT);

    dim3 blk(256);

    // Prep
    rope_table_kernel<<<(SEQ * (CH / 2) + 255) / 256, 256>>>();
    zero_l_kernel<<<(MTOT + 255) / 256, 256>>>();
    split_kernel<<<(MTOT * CH / 4 + 255) / 256, 256>>>(x, TB_XH, MTOT * CH / 4);
    dim3 gw(CH / 32, CH / 32, 4), bw(32, 8);
    wT_split_kernel<<<gw, bw>>>(Wq, Wk, Wv, Wo);

    // Fused Q/K/V projections
    dim3 gqkv(CH / 128, MTOT / 128, 3);
    qkv_kernel<<<gqkv, blk, SMEM_TOT>>>(bq, bk, bv);

    // Scores: exp(Q K^T / 32) causal-masked -> PH/PL hi/lo, row sums -> g_L
    const int nb = SEQ / 128;
    dim3 gsc(nb * (nb + 1) / 2, 1, BATCH);
    hmma_gemm<2, false, true, false, false, false><<<gsc, blk, SMEM_TOT>>>(
        TB_QH, TB_KH, CH, CH, TC, TC, nullptr, nullptr, SEQ, TT, 0, CH, 1.0f / 32.0f);

    // O = (exp(S) V) / l  (K-limited, LPT order, /l in epilogue)
    dim3 gpv(CH / 128, SEQ / 128, BATCH);
    hmma_gemm<1, false, false, true, true, true><<<gpv, blk, SMEM_TOT>>>(
        TB_PH, TB_VTH, SEQ, SEQ, TT, (long long)CH * SEQ, nullptr, nullptr,
        CH, TC, TB_OH, SEQ, 1.0f);

    // out = O Wo + bo
    dim3 gproj(CH / 128, MTOT / 128, 1);
    hmma_gemm<0, true, false, false, false, false><<<gproj, blk, SMEM_TOT>>>(
        TB_OH, TB_WOH, CH, CH, 0, 0, bo, out, CH, 0, 0, CH, 1.0f);
}

// round 11
// speedup vs baseline: 1.0267x; 1.0267x over previous
#include <cuda_runtime.h>
#include <cuda_bf16.h>
#include <math.h>
#include <stdint.h>

// Problem shape (fixed): B=4, T=2048, C=1024, fp32 in/out.
#define BATCH 4
#define SEQ   2048
#define CH    1024
#define MTOT  (BATCH*SEQ)          // 8192
#define PELEM (BATCH*SEQ*SEQ)      // 16777216

typedef __nv_bfloat16 bf16;

// ---------------------------------------------------------------------------
// Device-global scratch
// ---------------------------------------------------------------------------
__device__ __align__(128) bf16 g_XH[MTOT*CH],  g_XL[MTOT*CH];
__device__ __align__(128) bf16 g_WQH[CH*CH],   g_WQL[CH*CH];
__device__ __align__(128) bf16 g_WKH[CH*CH],   g_WKL[CH*CH];
__device__ __align__(128) bf16 g_WVH[CH*CH],   g_WVL[CH*CH];    // PLAIN Wv hi/lo
__device__ __align__(128) bf16 g_WOH[CH*CH],   g_WOL[CH*CH];    // Wo^T hi/lo
__device__ __align__(128) bf16 g_W2H[CH*CH],   g_W2L[CH*CH];    // (Wv·Wo)^T hi/lo
__device__ __align__(128) bf16 g_QH[MTOT*CH],  g_QL[MTOT*CH];
__device__ __align__(128) bf16 g_KH[MTOT*CH],  g_KL[MTOT*CH];
__device__ __align__(128) bf16 g_VWH[MTOT*CH], g_VWL[MTOT*CH];  // (V·Wo)^T [b][c][t]
__device__ __align__(128) bf16 g_PH[PELEM],    g_PL[PELEM];     // exp(S) hi/lo
__device__ __align__(128) float g_L[MTOT];                      // row sums of exp
__device__ __align__(128) float g_B2[CH];                       // bv·Wo
__device__ __align__(128) float2 g_ROPE[SEQ*(CH/2)];            // cos/sin table

#define TB_XH  0
#define TB_WQH 2
#define TB_WKH 4
#define TB_WVH 6
#define TB_WOH 8
#define TB_QH  10
#define TB_KH  12
#define TB_VWH 14
#define TB_PH  16
#define TB_W2H 18

__device__ __forceinline__ bf16* bbuf(int tag) {
    switch (tag) {
        case TB_XH:      return g_XH;  case TB_XH + 1:  return g_XL;
        case TB_WQH:     return g_WQH; case TB_WQH + 1: return g_WQL;
        case TB_WKH:     return g_WKH; case TB_WKH + 1: return g_WKL;
        case TB_WVH:     return g_WVH; case TB_WVH + 1: return g_WVL;
        case TB_WOH:     return g_WOH; case TB_WOH + 1: return g_WOL;
        case TB_QH:      return g_QH;  case TB_QH + 1:  return g_QL;
        case TB_KH:      return g_KH;  case TB_KH + 1:  return g_KL;
        case TB_VWH:     return g_VWH; case TB_VWH + 1: return g_VWL;
        case TB_PH:      return g_PH;  case TB_PH + 1:  return g_PL;
        case TB_W2H:     return g_W2H; case TB_W2H + 1: return g_W2L;
        default:         return g_XH;
    }
}

// ---------------------------------------------------------------------------
// PTX helpers (arch-agnostic at plain sm_100)
// ---------------------------------------------------------------------------
__device__ __forceinline__ uint32_t s2u(const void* p) {
    uint32_t a;
    asm("{ .reg .u64 t; cvta.to.shared.u64 t, %1; cvt.u32.u64 %0, t; }" : "=r"(a) : "l"(p));
    return a;
}
__device__ __forceinline__ void cp16(uint32_t dst, const void* src) {
    asm volatile("cp.async.cg.shared.global [%0], [%1], 16;" :: "r"(dst), "l"(src) : "memory");
}
__device__ __forceinline__ void cp_commit() {
    asm volatile("cp.async.commit_group;" ::: "memory");
}
__device__ __forceinline__ void ldsm4(uint32_t& r0, uint32_t& r1, uint32_t& r2, uint32_t& r3,
                                      uint32_t addr) {
    asm volatile("ldmatrix.sync.aligned.m8n8.x4.shared.b16 {%0,%1,%2,%3}, [%4];"
                 : "=r"(r0), "=r"(r1), "=r"(r2), "=r"(r3) : "r"(addr));
}
__device__ __forceinline__ void mma16816(float* c, const uint32_t* a, const uint32_t* b) {
    asm volatile(
        "mma.sync.aligned.m16n8k16.row.col.f32.bf16.bf16.f32 "
        "{%0,%1,%2,%3}, {%4,%5,%6,%7}, {%8,%9}, {%0,%1,%2,%3};"
        : "+f"(c[0]), "+f"(c[1]), "+f"(c[2]), "+f"(c[3])
        : "r"(a[0]), "r"(a[1]), "r"(a[2]), "r"(a[3]), "r"(b[0]), "r"(b[1]));
}
__device__ __forceinline__ void split2(float v, bf16& h, bf16& l) {
    h = __float2bfloat16(v);
    l = __float2bfloat16(v - __bfloat162float(h));
}
__device__ __forceinline__ uint32_t pack2(bf16 a, bf16 b) {
    uint16_t x = *(uint16_t*)&a, y = *(uint16_t*)&b;
    return (uint32_t)x | ((uint32_t)y << 16);
}

// ---------------------------------------------------------------------------
// Swizzled smem layout: tile = 128 rows x 32 bf16 (64B/row), no padding.
// ---------------------------------------------------------------------------
__device__ __forceinline__ uint32_t swz(uint32_t row, uint32_t kseg) {
    return row * 64u + ((kseg ^ ((row >> 1) & 3u)) * 16u);
}

#define NSTG    3
#define TILE_B  8192                     // 128*64B
#define STAGE_B (4*TILE_B)               // Ah,Al,Bh,Bl = 32768
#define SMEM_TOT (NSTG*STAGE_B)          // 98304

// ---------------------------------------------------------------------------
// Mainloop (R8 schedule — the proven one): acc += A[M,K] @ B[N,K]^T, hi/lo
// split (Ah·Bl -> Ah·Bh -> Al·Bh), tile 128x128, BK=32, 8 warps, 3-stage
// cp.async, single sync per chunk; af+bh front-loaded, bt in pass 1, al in
// pass 3; next-chunk cp.async split across the two ks halves.
// ---------------------------------------------------------------------------
template <bool KLIM>
__device__ __forceinline__ void hmma_mainloop(
    float (&acc)[2][8][4],
    const bf16* __restrict__ Ah, const bf16* __restrict__ Al,
    const bf16* __restrict__ Bh, const bf16* __restrict__ Bl,
    int ldA, int ldB, int bm, int bn, int Ktot, uint32_t sb) {

    const int tid = threadIdx.x;
    const int wid = tid >> 5, lane = tid & 31;
    const int wm = wid & 3, wn = wid >> 2;

    const int lrow = tid >> 1;
    const int k2   = (tid & 1) * 2;
    const uint32_t s0 = swz(lrow, k2);
    const uint32_t s1 = swz(lrow, k2 + 1);
    const long long aRow = (long long)(bm * 128 + lrow) * ldA + k2 * 8;
    const long long bRow = (long long)(bn * 128 + lrow) * ldB + k2 * 8;

    const int Kend = KLIM ? min(Ktot, (bm + 1) * 128) : Ktot;
    const int nch  = Kend >> 5;

    auto issueA = [&](int kt, int stage) {
        const uint32_t d = sb + (uint32_t)stage * STAGE_B;
        const long long g = (long long)kt * 32;
        const bf16* pah = Ah + aRow + g;
        const bf16* pal = Al + aRow + g;
        cp16(d + s0,          pah);  cp16(d + s1,          pah + 8);
        cp16(d + TILE_B + s0, pal);  cp16(d + TILE_B + s1, pal + 8);
    };
    auto issueB = [&](int kt, int stage) {
        const uint32_t d = sb + (uint32_t)stage * STAGE_B;
        const long long g = (long long)kt * 32;
        const bf16* pbh = Bh + bRow + g;
        const bf16* pbl = Bl + bRow + g;
        cp16(d + 2 * TILE_B + s0, pbh);  cp16(d + 2 * TILE_B + s1, pbh + 8);
        cp16(d + 3 * TILE_B + s0, pbl);  cp16(d + 3 * TILE_B + s1, pbl + 8);
        cp_commit();
    };

    const int la_row = (lane & 7) + ((lane >> 3) & 1) * 8;
    const int la_ks  = (lane >> 4) & 1;
    const int lb_row = (lane & 7) + ((lane >> 4) & 1) * 8;
    const int lb_ks  = (lane >> 3) & 1;

    issueA(0, 0); issueB(0, 0);
    if (1 < nch) { issueA(1, 1); issueB(1, 1); }

    int st = 0;
    for (int kt = 0; kt < nch; kt++) {
        if (kt + 1 < nch) {
            asm volatile("cp.async.wait_group 1;" ::: "memory");
        } else {
            asm volatile("cp.async.wait_group 0;" ::: "memory");
        }
        __syncthreads();

        const bool pre = (kt + 2 < nch);
        const int  st2 = (st + 2 >= NSTG) ? st + 2 - NSTG : st + 2;

        const uint32_t aHi = sb + (uint32_t)st * STAGE_B;
        const uint32_t aLo = aHi + TILE_B;
        const uint32_t bHi = aHi + 2 * TILE_B;
        const uint32_t bLo = aHi + 3 * TILE_B;

#pragma unroll
        for (int ks = 0; ks < 2; ks++) {
            const uint32_t ka = (uint32_t)(ks * 2 + la_ks);
            const uint32_t kb = (uint32_t)(ks * 2 + lb_ks);

            uint32_t af[2][4];
#pragma unroll
            for (int i = 0; i < 2; i++)
                ldsm4(af[i][0], af[i][1], af[i][2], af[i][3],
                      aHi + swz((uint32_t)(wm * 32 + i * 16 + la_row), ka));
            uint32_t bh[4][4];
#pragma unroll
            for (int p = 0; p < 4; p++)
                ldsm4(bh[p][0], bh[p][1], bh[p][2], bh[p][3],
                      bHi + swz((uint32_t)(wn * 64 + p * 16 + lb_row), kb));

            {   // pass 1: Ah x Bl
                uint32_t bt[4][4];
#pragma unroll
                for (int p = 0; p < 4; p++)
                    ldsm4(bt[p][0], bt[p][1], bt[p][2], bt[p][3],
                          bLo + swz((uint32_t)(wn * 64 + p * 16 + lb_row), kb));
#pragma unroll
                for (int i = 0; i < 2; i++)
#pragma unroll
                    for (int p = 0; p < 4; p++) {
                        mma16816(acc[i][p * 2 + 0], af[i], &bt[p][0]);
                        mma16816(acc[i][p * 2 + 1], af[i], &bt[p][2]);
                    }
            }

            if (pre) { if (ks == 0) issueA(kt + 2, st2); else issueB(kt + 2, st2); }

            // pass 2: Ah x Bh
#pragma unroll
            for (int i = 0; i < 2; i++)
#pragma unroll
                for (int p = 0; p < 4; p++) {
                    mma16816(acc[i][p * 2 + 0], af[i], &bh[p][0]);
                    mma16816(acc[i][p * 2 + 1], af[i], &bh[p][2]);
                }

            {   // pass 3: Al x Bh
                uint32_t al[2][4];
#pragma unroll
                for (int i = 0; i < 2; i++)
                    ldsm4(al[i][0], al[i][1], al[i][2], al[i][3],
                          aLo + swz((uint32_t)(wm * 32 + i * 16 + la_row), ka));
#pragma unroll
                for (int i = 0; i < 2; i++)
#pragma unroll
                    for (int p = 0; p < 4; p++) {
                        mma16816(acc[i][p * 2 + 0], al[i], &bh[p][0]);
                        mma16816(acc[i][p * 2 + 1], al[i], &bh[p][2]);
                    }
            }
        }
        st = (st + 1 == NSTG) ? 0 : st + 1;
    }
}

// ---------------------------------------------------------------------------
// Fused projections: z = 0/1 -> (Wq/Wk, RoPE -> Q/K hi/lo),
//                    z = 2   -> (W2 = Wv·Wo, +b2 -> VW^T hi/lo, transposed)
// ---------------------------------------------------------------------------
__global__ void __launch_bounds__(256, 2)
qkv_kernel(const float* __restrict__ bq, const float* __restrict__ bk) {
    const int bm = blockIdx.y, bn = blockIdx.x, z = blockIdx.z;

    extern __shared__ char smem[];
    const uint32_t sb = s2u(smem);
    const int tid = threadIdx.x, wid = tid >> 5, lane = tid & 31;
    const int wm = wid & 3, wn = wid >> 2;

    const int wtag = (z == 0) ? TB_WQH : (z == 1) ? TB_WKH : TB_W2H;
    const float* bias = (z == 0) ? bq : (z == 1) ? bk : g_B2;

    float acc[2][8][4];
#pragma unroll
    for (int i = 0; i < 2; i++)
#pragma unroll
        for (int j = 0; j < 8; j++)
#pragma unroll
            for (int q = 0; q < 4; q++) acc[i][j][q] = 0.0f;

    hmma_mainloop<false>(acc, g_XH, g_XL, bbuf(wtag), bbuf(wtag + 1),
                         CH, CH, bm, bn, CH, sb);

    const int rbase = bm * 128 + wm * 32 + (lane >> 2);
    const int cbase = bn * 128 + wn * 64 + (lane & 3) * 2;
#pragma unroll
    for (int i = 0; i < 2; i++) {
#pragma unroll
        for (int h = 0; h < 2; h++) {
            const int r = rbase + i * 16 + h * 8;
            const int t = r & (SEQ - 1);
            const float2* tab = g_ROPE + (long long)t * (CH / 2);
#pragma unroll
            for (int j = 0; j < 8; j++) {
                const int c = cbase + j * 8;
                float v0 = acc[i][j][h * 2 + 0] + bias[c];
                float v1 = acc[i][j][h * 2 + 1] + bias[c + 1];
                if (z < 2) {
                    float2 cs = tab[c >> 1];
                    float e = v0, o = v1;
                    v0 = e * cs.x - o * cs.y;
                    v1 = o * cs.x + e * cs.y;
                    bf16 h0, l0, h1, l1;
                    split2(v0, h0, l0);
                    split2(v1, h1, l1);
                    bf16* H = (z == 0) ? g_QH : g_KH;
                    bf16* L = (z == 0) ? g_QL : g_KL;
                    const long long idx = (long long)r * CH + c;
                    *(uint32_t*)(H + idx) = pack2(h0, h1);
                    *(uint32_t*)(L + idx) = pack2(l0, l1);
                } else {
                    const int b = r >> 11, tq = r & (SEQ - 1);
                    bf16 h0, l0, h1, l1;
                    split2(v0, h0, l0);
                    split2(v1, h1, l1);
                    const long long i0 = ((long long)b * CH + c) * SEQ + tq;
                    const long long i1 = ((long long)b * CH + c + 1) * SEQ + tq;
                    g_VWH[i0] = h0; g_VWL[i0] = l0;
                    g_VWH[i1] = h1; g_VWL[i1] = l1;
                }
            }
        }
    }
}

// ---------------------------------------------------------------------------
// Generic GEMM.
//   OUT_MODE: 0 = fp32 to cext (+bias, LSCALE: /g_L)   [PV -> final out]
//             1 = bf16 hi/lo to tagOut                 [W2 precompute]
//             2 = exp(S*alpha) causal-masked -> PH/PL hi/lo + row-sum atomics
//   CAUSAL:   1D triangular grid decode; REV: reverse bm (LPT for PV)
// ---------------------------------------------------------------------------
template <int OUT_MODE, bool BIAS, bool CAUSAL, bool KLIM, bool REV, bool LSCALE>
__global__ void __launch_bounds__(256, 2)
hmma_gemm(int tagA, int tagB, int ldA, int ldB, long long sA, long long sB,
          const float* __restrict__ bias, float* __restrict__ cext,
          int ldC, long long sC, int tagOut, int Ktot, float alpha) {
    int bm, bn;
    if (CAUSAL) {
        const int x = blockIdx.x;
        int r = (int)((sqrtf(8.0f * x + 1.0f) - 1.0f) * 0.5f);
        while ((r + 1) * (r + 2) / 2 <= x) r++;
        while (r * (r + 1) / 2 > x) r--;
        bm = r;
        bn = x - r * (r + 1) / 2;
    } else {
        bm = REV ? (int)(gridDim.y - 1 - blockIdx.y) : (int)blockIdx.y;
        bn = blockIdx.x;
    }
    const int z = blockIdx.z;

    extern __shared__ char smem[];
    const uint32_t sb = s2u(smem);
    const int tid = threadIdx.x, wid = tid >> 5, lane = tid & 31;
    const int wm = wid & 3, wn = wid >> 2;

    const bf16* Ah = bbuf(tagA)     + (long long)z * sA;
    const bf16* Al = bbuf(tagA + 1) + (long long)z * sA;
    const bf16* Bh = bbuf(tagB)     + (long long)z * sB;
    const bf16* Bl = bbuf(tagB + 1) + (long long)z * sB;

    float acc[2][8][4];
#pragma unroll
    for (int i = 0; i < 2; i++)
#pragma unroll
        for (int j = 0; j < 8; j++)
#pragma unroll
            for (int q = 0; q < 4; q++) acc[i][j][q] = 0.0f;

    hmma_mainloop<KLIM>(acc, Ah, Al, Bh, Bl, ldA, ldB, bm, bn, Ktot, sb);

    const int rbase = bm * 128 + wm * 32 + (lane >> 2);
    const int cbase = bn * 128 + wn * 64 + (lane & 3) * 2;

    if (OUT_MODE == 2) {
        bf16* PH = g_PH + (long long)z * sC;
        bf16* PL = g_PL + (long long)z * sC;
        float rsum[2][2];
        rsum[0][0] = rsum[0][1] = rsum[1][0] = rsum[1][1] = 0.0f;
#pragma unroll
        for (int i = 0; i < 2; i++) {
#pragma unroll
            for (int h = 0; h < 2; h++) {
                const int r = rbase + i * 16 + h * 8;
#pragma unroll
                for (int j = 0; j < 8; j++) {
                    const int c = cbase + j * 8;
                    float e0 = (c     <= r) ? __expf(acc[i][j][h * 2 + 0] * alpha) : 0.0f;
                    float e1 = (c + 1 <= r) ? __expf(acc[i][j][h * 2 + 1] * alpha) : 0.0f;
                    bf16 h0, l0, h1, l1;
                    split2(e0, h0, l0);
                    split2(e1, h1, l1);
                    const long long idx = (long long)r * ldC + c;
                    *(uint32_t*)(PH + idx) = pack2(h0, h1);
                    *(uint32_t*)(PL + idx) = pack2(l0, l1);
                    rsum[i][h] += e0 + e1;
                }
            }
        }
#pragma unroll
        for (int i = 0; i < 2; i++)
#pragma unroll
            for (int h = 0; h < 2; h++) {
                float s = rsum[i][h];
                s += __shfl_xor_sync(0xffffffffu, s, 1);
                s += __shfl_xor_sync(0xffffffffu, s, 2);
                if ((lane & 3) == 0)
                    atomicAdd(&g_L[z * SEQ + rbase + i * 16 + h * 8], s);
            }
        return;
    }

#pragma unroll
    for (int i = 0; i < 2; i++) {
#pragma unroll
        for (int h = 0; h < 2; h++) {
            const int r = rbase + i * 16 + h * 8;
            const float linv = LSCALE ? (1.0f / g_L[z * SEQ + r]) : 1.0f;
#pragma unroll
            for (int j = 0; j < 8; j++) {
                const int c = cbase + j * 8;
                float v0 = acc[i][j][h * 2 + 0] * alpha;
                float v1 = acc[i][j][h * 2 + 1] * alpha;
                if (LSCALE) { v0 *= linv; v1 *= linv; }
                if (BIAS) { v0 += bias[c]; v1 += bias[c + 1]; }
                if (OUT_MODE == 0) {
                    float* C = cext + (long long)z * sC;
                    *(float2*)(C + (long long)r * ldC + c) = make_float2(v0, v1);
                } else {
                    bf16 h0, l0, h1, l1;
                    split2(v0, h0, l0);
                    split2(v1, h1, l1);
                    bf16* H = bbuf(tagOut)     + (long long)z * sC;
                    bf16* L = bbuf(tagOut + 1) + (long long)z * sC;
                    const long long idx = (long long)r * ldC + c;
                    *(uint32_t*)(H + idx) = pack2(h0, h1);
                    *(uint32_t*)(L + idx) = pack2(l0, l1);
                }
            }
        }
    }
}

// ---------------------------------------------------------------------------
// RoPE table (reference-matching fp32 pipeline)
// ---------------------------------------------------------------------------
__global__ void rope_table_kernel() {
    int idx = blockIdx.x * blockDim.x + threadIdx.x;
    const int half = CH >> 1;
    if (idx >= SEQ * half) return;
    int t = idx / half, p = idx - t * half;
    float inv = 1.0f / powf(10000.0f, (float)(2 * p) / (float)CH);
    float s, c;
    sincosf((float)t * inv, &s, &c);
    g_ROPE[idx] = make_float2(c, s);
}

// zero g_L each launch (graph replays)
__global__ void zero_l_kernel() {
    int i = blockIdx.x * blockDim.x + threadIdx.x;
    if (i < MTOT) g_L[i] = 0.0f;
}

// b2 = bv · Wo  (b2[n] = sum_c bv[c] * Wo[c,n])
__global__ void b2_kernel(const float* __restrict__ bv, const float* __restrict__ Wo) {
    const int n = blockIdx.x * blockDim.x + threadIdx.x;
    if (n >= CH) return;
    float s = 0.0f;
    for (int c = 0; c < CH; c++) s += bv[c] * Wo[(long long)c * CH + n];
    g_B2[n] = s;
}

// fp32 -> bf16 hi/lo split (vectorized, NO transpose)
__global__ void split_kernel(const float* __restrict__ src, int tagHi, int n4) {
    int i = blockIdx.x * blockDim.x + threadIdx.x;
    if (i >= n4) return;
    float4 x = ((const float4*)src)[i];
    bf16 h[4], l[4];
    split2(x.x, h[0], l[0]); split2(x.y, h[1], l[1]);
    split2(x.z, h[2], l[2]); split2(x.w, h[3], l[3]);
    *(uint2*)(bbuf(tagHi)     + (long long)i * 4) = *(const uint2*)h;
    *(uint2*)(bbuf(tagHi + 1) + (long long)i * 4) = *(const uint2*)l;
}

// W [K,N] -> W^T hi/lo [N,K]; z = 0/1/2 -> Wq/Wk/Wo (Wv is NOT transposed)
__global__ void wT_split_kernel(const float* __restrict__ W0, const float* __restrict__ W1,
                                const float* __restrict__ W2) {
    __shared__ float tile[32][33];
    const int z = blockIdx.z;
    const float* W = (z == 0) ? W0 : (z == 1) ? W1 : W2;
    const int tagHi = (z == 0) ? TB_WQH : (z == 1) ? TB_WKH : TB_WOH;
    const int n0 = blockIdx.x * 32, k0 = blockIdx.y * 32;
    const int tx = threadIdx.x, ty = threadIdx.y;   // 32 x 8
#pragma unroll
    for (int i = 0; i < 32; i += 8)
        tile[ty + i][tx] = W[(long long)(k0 + ty + i) * CH + n0 + tx];
    __syncthreads();
    bf16* H = bbuf(tagHi);
    bf16* L = bbuf(tagHi + 1);
#pragma unroll
    for (int i = 0; i < 32; i += 8) {
        bf16 h, l;
        split2(tile[tx][ty + i], h, l);
        const long long idx = (long long)(n0 + ty + i) * CH + k0 + tx;
        H[idx] = h;
        L[idx] = l;
    }
}

// ---------------------------------------------------------------------------
// Launch
// ---------------------------------------------------------------------------
extern "C" void kernel_launch(void* const* d_in, const int* in_sizes, int n_in,
                              void* d_out, int out_size) {
    const float* x  = (const float*)d_in[0];
    const float* Wq = (const float*)d_in[1];
    const float* bq = (const float*)d_in[2];
    const float* Wk = (const float*)d_in[3];
    const float* bk = (const float*)d_in[4];
    const float* Wv = (const float*)d_in[5];
    const float* bv = (const float*)d_in[6];
    const float* Wo = (const float*)d_in[7];
    const float* bo = (const float*)d_in[8];
    float* out = (float*)d_out;

    const long long TC = (long long)SEQ * CH;
    const long long TT = (long long)SEQ * SEQ;

    cudaFuncSetAttribute(qkv_kernel,
                         cudaFuncAttributeMaxDynamicSharedMemorySize, SMEM_TOT);
    cudaFuncSetAttribute(hmma_gemm<1, false, false, false, false, false>,
                         cudaFuncAttributeMaxDynamicSharedMemorySize, SMEM_TOT);
    cudaFuncSetAttribute(hmma_gemm<2, false, true,  false, false, false>,
                         cudaFuncAttributeMaxDynamicSharedMemorySize, SMEM_TOT);
    cudaFuncSetAttribute(hmma_gemm<0, true,  false, true,  true,  true>,
                         cudaFuncAttributeMaxDynamicSharedMemorySize, SMEM_TOT);

    dim3 blk(256);

    // Prep
    rope_table_kernel<<<(SEQ * (CH / 2) + 255) / 256, 256>>>();
    zero_l_kernel<<<(MTOT + 255) / 256, 256>>>();
    b2_kernel<<<CH / 256, 256>>>(bv, Wo);
    split_kernel<<<(MTOT * CH / 4 + 255) / 256, 256>>>(x, TB_XH, MTOT * CH / 4);
    split_kernel<<<(CH * CH / 4 + 255) / 256, 256>>>(Wv, TB_WVH, CH * CH / 4);  // plain Wv
    dim3 gw(CH / 32, CH / 32, 3), bw(32, 8);
    wT_split_kernel<<<gw, bw>>>(Wq, Wk, Wo);

    // W2^T[n',k'] = sum_c Wo[c,n']*Wv[k',c]:  A = Wo^T, B = plain Wv
    dim3 gw2(CH / 128, CH / 128, 1);
    hmma_gemm<1, false, false, false, false, false><<<gw2, blk, SMEM_TOT>>>(
        TB_WOH, TB_WVH, CH, CH, 0, 0, nullptr, nullptr, CH, 0, TB_W2H, CH, 1.0f);

    // Fused projections: Q (RoPE), K (RoPE), VW = X·W2 + b2 (transposed)
    dim3 gqkv(CH / 128, MTOT / 128, 3);
    qkv_kernel<<<gqkv, blk, SMEM_TOT>>>(bq, bk);

    // Scores: exp(Q K^T / 32) causal-masked -> PH/PL hi/lo, row sums -> g_L
    const int nb = SEQ / 128;
    dim3 gsc(nb * (nb + 1) / 2, 1, BATCH);
    hmma_gemm<2, false, true, false, false, false><<<gsc, blk, SMEM_TOT>>>(
        TB_QH, TB_KH, CH, CH, TC, TC, nullptr, nullptr, SEQ, TT, 0, CH, 1.0f / 32.0f);

    // Final: out = (exp(S) · VW)/l + bo  (K-limited, LPT order)
    dim3 gpv(CH / 128, SEQ / 128, BATCH);
    hmma_gemm<0, true, false, true, true, true><<<gpv, blk, SMEM_TOT>>>(
        TB_PH, TB_VWH, SEQ, SEQ, TT, (long long)CH * SEQ, bo, out,
        CH, TC, 0, SEQ, 1.0f);
}

// round 12
// speedup vs baseline: 1.1447x; 1.1150x over previous
#include <cuda_runtime.h>
#include <cuda_bf16.h>
#include <math.h>
#include <stdint.h>

// Problem shape (fixed): B=4, T=2048, C=1024, fp32 in/out.
#define BATCH 4
#define SEQ   2048
#define CH    1024
#define MTOT  (BATCH*SEQ)          // 8192
#define PELEM (BATCH*SEQ*SEQ)      // 16777216

typedef __nv_bfloat16 bf16;

// ---------------------------------------------------------------------------
// Device-global scratch
// ---------------------------------------------------------------------------
__device__ __align__(128) bf16 g_XH[MTOT*CH],  g_XL[MTOT*CH];
__device__ __align__(128) bf16 g_WQH[CH*CH],   g_WQL[CH*CH];
__device__ __align__(128) bf16 g_WKH[CH*CH],   g_WKL[CH*CH];
__device__ __align__(128) bf16 g_WVH[CH*CH],   g_WVL[CH*CH];    // PLAIN Wv hi/lo
__device__ __align__(128) bf16 g_WOH[CH*CH],   g_WOL[CH*CH];    // Wo^T hi/lo
__device__ __align__(128) bf16 g_W2H[CH*CH],   g_W2L[CH*CH];    // (Wv·Wo)^T hi/lo
__device__ __align__(128) bf16 g_QH[MTOT*CH],  g_QL[MTOT*CH];
__device__ __align__(128) bf16 g_KH[MTOT*CH],  g_KL[MTOT*CH];
__device__ __align__(128) bf16 g_VWH[MTOT*CH], g_VWL[MTOT*CH];  // (V·Wo)^T [b][c][t]
__device__ __align__(128) bf16 g_PH[PELEM],    g_PL[PELEM];     // exp(S) hi/lo
__device__ __align__(128) float g_L[MTOT];                      // row sums of exp
__device__ __align__(128) float g_B2[CH];                       // bv·Wo
__device__ __align__(128) float2 g_ROPE[SEQ*(CH/2)];            // cos/sin table

#define TB_XH  0
#define TB_WQH 2
#define TB_WKH 4
#define TB_WVH 6
#define TB_WOH 8
#define TB_QH  10
#define TB_KH  12
#define TB_VWH 14
#define TB_PH  16
#define TB_W2H 18

__device__ __forceinline__ bf16* bbuf(int tag) {
    switch (tag) {
        case TB_XH:      return g_XH;  case TB_XH + 1:  return g_XL;
        case TB_WQH:     return g_WQH; case TB_WQH + 1: return g_WQL;
        case TB_WKH:     return g_WKH; case TB_WKH + 1: return g_WKL;
        case TB_WVH:     return g_WVH; case TB_WVH + 1: return g_WVL;
        case TB_WOH:     return g_WOH; case TB_WOH + 1: return g_WOL;
        case TB_QH:      return g_QH;  case TB_QH + 1:  return g_QL;
        case TB_KH:      return g_KH;  case TB_KH + 1:  return g_KL;
        case TB_VWH:     return g_VWH; case TB_VWH + 1: return g_VWL;
        case TB_PH:      return g_PH;  case TB_PH + 1:  return g_PL;
        case TB_W2H:     return g_W2H; case TB_W2H + 1: return g_W2L;
        default:         return g_XH;
    }
}

// ---------------------------------------------------------------------------
// PTX helpers (arch-agnostic at plain sm_100)
// ---------------------------------------------------------------------------
__device__ __forceinline__ uint32_t s2u(const void* p) {
    uint32_t a;
    asm("{ .reg .u64 t; cvta.to.shared.u64 t, %1; cvt.u32.u64 %0, t; }" : "=r"(a) : "l"(p));
    return a;
}
__device__ __forceinline__ void cp16(uint32_t dst, const void* src) {
    asm volatile("cp.async.cg.shared.global [%0], [%1], 16;" :: "r"(dst), "l"(src) : "memory");
}
__device__ __forceinline__ void cp_commit() {
    asm volatile("cp.async.commit_group;" ::: "memory");
}
__device__ __forceinline__ void ldsm4(uint32_t& r0, uint32_t& r1, uint32_t& r2, uint32_t& r3,
                                      uint32_t addr) {
    asm volatile("ldmatrix.sync.aligned.m8n8.x4.shared.b16 {%0,%1,%2,%3}, [%4];"
                 : "=r"(r0), "=r"(r1), "=r"(r2), "=r"(r3) : "r"(addr));
}
__device__ __forceinline__ void mma16816(float* c, const uint32_t* a, const uint32_t* b) {
    asm volatile(
        "mma.sync.aligned.m16n8k16.row.col.f32.bf16.bf16.f32 "
        "{%0,%1,%2,%3}, {%4,%5,%6,%7}, {%8,%9}, {%0,%1,%2,%3};"
        : "+f"(c[0]), "+f"(c[1]), "+f"(c[2]), "+f"(c[3])
        : "r"(a[0]), "r"(a[1]), "r"(a[2]), "r"(a[3]), "r"(b[0]), "r"(b[1]));
}
__device__ __forceinline__ void split2(float v, bf16& h, bf16& l) {
    h = __float2bfloat16(v);
    l = __float2bfloat16(v - __bfloat162float(h));
}
__device__ __forceinline__ uint32_t pack2(bf16 a, bf16 b) {
    uint16_t x = *(uint16_t*)&a, y = *(uint16_t*)&b;
    return (uint32_t)x | ((uint32_t)y << 16);
}

// ---------------------------------------------------------------------------
// Swizzled smem layout: tile = 128 rows x 32 bf16 (64B/row), no padding.
// ---------------------------------------------------------------------------
__device__ __forceinline__ uint32_t swz(uint32_t row, uint32_t kseg) {
    return row * 64u + ((kseg ^ ((row >> 1) & 3u)) * 16u);
}

#define NSTG    3
#define TILE_B  8192                     // 128*64B
#define STAGE_B (4*TILE_B)               // Ah,Al,Bh,Bl = 32768
#define SMEM_TOT (NSTG*STAGE_B)          // 98304

// ---------------------------------------------------------------------------
// Mainloop (R8 schedule — frozen): acc += A[M,K] @ B[N,K]^T, hi/lo split
// (Ah·Bl -> Ah·Bh -> Al·Bh), tile 128x128, BK=32, 8 warps, 3-stage cp.async,
// single sync per chunk; af+bh front-loaded, bt in pass 1, al in pass 3;
// next-chunk cp.async split across the two ks halves.
// ---------------------------------------------------------------------------
template <bool KLIM>
__device__ __forceinline__ void hmma_mainloop(
    float (&acc)[2][8][4],
    const bf16* __restrict__ Ah, const bf16* __restrict__ Al,
    const bf16* __restrict__ Bh, const bf16* __restrict__ Bl,
    int ldA, int ldB, int bm, int bn, int Ktot, uint32_t sb) {

    const int tid = threadIdx.x;
    const int wid = tid >> 5, lane = tid & 31;
    const int wm = wid & 3, wn = wid >> 2;

    const int lrow = tid >> 1;
    const int k2   = (tid & 1) * 2;
    const uint32_t s0 = swz(lrow, k2);
    const uint32_t s1 = swz(lrow, k2 + 1);
    const long long aRow = (long long)(bm * 128 + lrow) * ldA + k2 * 8;
    const long long bRow = (long long)(bn * 128 + lrow) * ldB + k2 * 8;

    const int Kend = KLIM ? min(Ktot, (bm + 1) * 128) : Ktot;
    const int nch  = Kend >> 5;

    auto issueA = [&](int kt, int stage) {
        const uint32_t d = sb + (uint32_t)stage * STAGE_B;
        const long long g = (long long)kt * 32;
        const bf16* pah = Ah + aRow + g;
        const bf16* pal = Al + aRow + g;
        cp16(d + s0,          pah);  cp16(d + s1,          pah + 8);
        cp16(d + TILE_B + s0, pal);  cp16(d + TILE_B + s1, pal + 8);
    };
    auto issueB = [&](int kt, int stage) {
        const uint32_t d = sb + (uint32_t)stage * STAGE_B;
        const long long g = (long long)kt * 32;
        const bf16* pbh = Bh + bRow + g;
        const bf16* pbl = Bl + bRow + g;
        cp16(d + 2 * TILE_B + s0, pbh);  cp16(d + 2 * TILE_B + s1, pbh + 8);
        cp16(d + 3 * TILE_B + s0, pbl);  cp16(d + 3 * TILE_B + s1, pbl + 8);
        cp_commit();
    };

    const int la_row = (lane & 7) + ((lane >> 3) & 1) * 8;
    const int la_ks  = (lane >> 4) & 1;
    const int lb_row = (lane & 7) + ((lane >> 4) & 1) * 8;
    const int lb_ks  = (lane >> 3) & 1;

    issueA(0, 0); issueB(0, 0);
    if (1 < nch) { issueA(1, 1); issueB(1, 1); }

    int st = 0;
    for (int kt = 0; kt < nch; kt++) {
        if (kt + 1 < nch) {
            asm volatile("cp.async.wait_group 1;" ::: "memory");
        } else {
            asm volatile("cp.async.wait_group 0;" ::: "memory");
        }
        __syncthreads();

        const bool pre = (kt + 2 < nch);
        const int  st2 = (st + 2 >= NSTG) ? st + 2 - NSTG : st + 2;

        const uint32_t aHi = sb + (uint32_t)st * STAGE_B;
        const uint32_t aLo = aHi + TILE_B;
        const uint32_t bHi = aHi + 2 * TILE_B;
        const uint32_t bLo = aHi + 3 * TILE_B;

#pragma unroll
        for (int ks = 0; ks < 2; ks++) {
            const uint32_t ka = (uint32_t)(ks * 2 + la_ks);
            const uint32_t kb = (uint32_t)(ks * 2 + lb_ks);

            uint32_t af[2][4];
#pragma unroll
            for (int i = 0; i < 2; i++)
                ldsm4(af[i][0], af[i][1], af[i][2], af[i][3],
                      aHi + swz((uint32_t)(wm * 32 + i * 16 + la_row), ka));
            uint32_t bh[4][4];
#pragma unroll
            for (int p = 0; p < 4; p++)
                ldsm4(bh[p][0], bh[p][1], bh[p][2], bh[p][3],
                      bHi + swz((uint32_t)(wn * 64 + p * 16 + lb_row), kb));

            {   // pass 1: Ah x Bl
                uint32_t bt[4][4];
#pragma unroll
                for (int p = 0; p < 4; p++)
                    ldsm4(bt[p][0], bt[p][1], bt[p][2], bt[p][3],
                          bLo + swz((uint32_t)(wn * 64 + p * 16 + lb_row), kb));
#pragma unroll
                for (int i = 0; i < 2; i++)
#pragma unroll
                    for (int p = 0; p < 4; p++) {
                        mma16816(acc[i][p * 2 + 0], af[i], &bt[p][0]);
                        mma16816(acc[i][p * 2 + 1], af[i], &bt[p][2]);
                    }
            }

            if (pre) { if (ks == 0) issueA(kt + 2, st2); else issueB(kt + 2, st2); }

            // pass 2: Ah x Bh
#pragma unroll
            for (int i = 0; i < 2; i++)
#pragma unroll
                for (int p = 0; p < 4; p++) {
                    mma16816(acc[i][p * 2 + 0], af[i], &bh[p][0]);
                    mma16816(acc[i][p * 2 + 1], af[i], &bh[p][2]);
                }

            {   // pass 3: Al x Bh
                uint32_t al[2][4];
#pragma unroll
                for (int i = 0; i < 2; i++)
                    ldsm4(al[i][0], al[i][1], al[i][2], al[i][3],
                          aLo + swz((uint32_t)(wm * 32 + i * 16 + la_row), ka));
#pragma unroll
                for (int i = 0; i < 2; i++)
#pragma unroll
                    for (int p = 0; p < 4; p++) {
                        mma16816(acc[i][p * 2 + 0], al[i], &bh[p][0]);
                        mma16816(acc[i][p * 2 + 1], al[i], &bh[p][2]);
                    }
            }
        }
        st = (st + 1 == NSTG) ? 0 : st + 1;
    }
}

// ---------------------------------------------------------------------------
// Fused projections: z = 0/1 -> (Wq/Wk, RoPE -> Q/K hi/lo),
//                    z = 2   -> (W2 = Wv·Wo, +b2 -> VW^T hi/lo, transposed)
// ---------------------------------------------------------------------------
__global__ void __launch_bounds__(256, 2)
qkv_kernel(const float* __restrict__ bq, const float* __restrict__ bk) {
    const int bm = blockIdx.y, bn = blockIdx.x, z = blockIdx.z;

    extern __shared__ char smem[];
    const uint32_t sb = s2u(smem);
    const int tid = threadIdx.x, wid = tid >> 5, lane = tid & 31;
    const int wm = wid & 3, wn = wid >> 2;

    const int wtag = (z == 0) ? TB_WQH : (z == 1) ? TB_WKH : TB_W2H;
    const float* bias = (z == 0) ? bq : (z == 1) ? bk : g_B2;

    float acc[2][8][4];
#pragma unroll
    for (int i = 0; i < 2; i++)
#pragma unroll
        for (int j = 0; j < 8; j++)
#pragma unroll
            for (int q = 0; q < 4; q++) acc[i][j][q] = 0.0f;

    hmma_mainloop<false>(acc, g_XH, g_XL, bbuf(wtag), bbuf(wtag + 1),
                         CH, CH, bm, bn, CH, sb);

    const int rbase = bm * 128 + wm * 32 + (lane >> 2);
    const int cbase = bn * 128 + wn * 64 + (lane & 3) * 2;
#pragma unroll
    for (int i = 0; i < 2; i++) {
#pragma unroll
        for (int h = 0; h < 2; h++) {
            const int r = rbase + i * 16 + h * 8;
            const int t = r & (SEQ - 1);
            const float2* tab = g_ROPE + (long long)t * (CH / 2);
#pragma unroll
            for (int j = 0; j < 8; j++) {
                const int c = cbase + j * 8;
                float v0 = acc[i][j][h * 2 + 0] + bias[c];
                float v1 = acc[i][j][h * 2 + 1] + bias[c + 1];
                if (z < 2) {
                    float2 cs = tab[c >> 1];
                    float e = v0, o = v1;
                    v0 = e * cs.x - o * cs.y;
                    v1 = o * cs.x + e * cs.y;
                    bf16 h0, l0, h1, l1;
                    split2(v0, h0, l0);
                    split2(v1, h1, l1);
                    bf16* H = (z == 0) ? g_QH : g_KH;
                    bf16* L = (z == 0) ? g_QL : g_KL;
                    const long long idx = (long long)r * CH + c;
                    *(uint32_t*)(H + idx) = pack2(h0, h1);
                    *(uint32_t*)(L + idx) = pack2(l0, l1);
                } else {
                    const int b = r >> 11, tq = r & (SEQ - 1);
                    bf16 h0, l0, h1, l1;
                    split2(v0, h0, l0);
                    split2(v1, h1, l1);
                    const long long i0 = ((long long)b * CH + c) * SEQ + tq;
                    const long long i1 = ((long long)b * CH + c + 1) * SEQ + tq;
                    g_VWH[i0] = h0; g_VWL[i0] = l0;
                    g_VWH[i1] = h1; g_VWL[i1] = l1;
                }
            }
        }
    }
}

// ---------------------------------------------------------------------------
// Generic GEMM.
//   OUT_MODE: 0 = fp32 to cext (+bias, LSCALE: /g_L)   [PV -> final out]
//             1 = bf16 hi/lo to tagOut                 [W2 precompute]
//             2 = exp(S*alpha) causal-masked -> PH/PL hi/lo + row-sum atomics
//   CAUSAL:   1D triangular grid decode; REV: reverse bm (LPT for PV)
// ---------------------------------------------------------------------------
template <int OUT_MODE, bool BIAS, bool CAUSAL, bool KLIM, bool REV, bool LSCALE>
__global__ void __launch_bounds__(256, 2)
hmma_gemm(int tagA, int tagB, int ldA, int ldB, long long sA, long long sB,
          const float* __restrict__ bias, float* __restrict__ cext,
          int ldC, long long sC, int tagOut, int Ktot, float alpha) {
    int bm, bn;
    if (CAUSAL) {
        const int x = blockIdx.x;
        int r = (int)((sqrtf(8.0f * x + 1.0f) - 1.0f) * 0.5f);
        while ((r + 1) * (r + 2) / 2 <= x) r++;
        while (r * (r + 1) / 2 > x) r--;
        bm = r;
        bn = x - r * (r + 1) / 2;
    } else {
        bm = REV ? (int)(gridDim.y - 1 - blockIdx.y) : (int)blockIdx.y;
        bn = blockIdx.x;
    }
    const int z = blockIdx.z;

    extern __shared__ char smem[];
    const uint32_t sb = s2u(smem);
    const int tid = threadIdx.x, wid = tid >> 5, lane = tid & 31;
    const int wm = wid & 3, wn = wid >> 2;

    const bf16* Ah = bbuf(tagA)     + (long long)z * sA;
    const bf16* Al = bbuf(tagA + 1) + (long long)z * sA;
    const bf16* Bh = bbuf(tagB)     + (long long)z * sB;
    const bf16* Bl = bbuf(tagB + 1) + (long long)z * sB;

    float acc[2][8][4];
#pragma unroll
    for (int i = 0; i < 2; i++)
#pragma unroll
        for (int j = 0; j < 8; j++)
#pragma unroll
            for (int q = 0; q < 4; q++) acc[i][j][q] = 0.0f;

    hmma_mainloop<KLIM>(acc, Ah, Al, Bh, Bl, ldA, ldB, bm, bn, Ktot, sb);

    const int rbase = bm * 128 + wm * 32 + (lane >> 2);
    const int cbase = bn * 128 + wn * 64 + (lane & 3) * 2;

    if (OUT_MODE == 2) {
        bf16* PH = g_PH + (long long)z * sC;
        bf16* PL = g_PL + (long long)z * sC;
        float rsum[2][2];
        rsum[0][0] = rsum[0][1] = rsum[1][0] = rsum[1][1] = 0.0f;
#pragma unroll
        for (int i = 0; i < 2; i++) {
#pragma unroll
            for (int h = 0; h < 2; h++) {
                const int r = rbase + i * 16 + h * 8;
#pragma unroll
                for (int j = 0; j < 8; j++) {
                    const int c = cbase + j * 8;
                    float e0 = (c     <= r) ? __expf(acc[i][j][h * 2 + 0] * alpha) : 0.0f;
                    float e1 = (c + 1 <= r) ? __expf(acc[i][j][h * 2 + 1] * alpha) : 0.0f;
                    bf16 h0, l0, h1, l1;
                    split2(e0, h0, l0);
                    split2(e1, h1, l1);
                    const long long idx = (long long)r * ldC + c;
                    *(uint32_t*)(PH + idx) = pack2(h0, h1);
                    *(uint32_t*)(PL + idx) = pack2(l0, l1);
                    rsum[i][h] += e0 + e1;
                }
            }
        }
#pragma unroll
        for (int i = 0; i < 2; i++)
#pragma unroll
            for (int h = 0; h < 2; h++) {
                float s = rsum[i][h];
                s += __shfl_xor_sync(0xffffffffu, s, 1);
                s += __shfl_xor_sync(0xffffffffu, s, 2);
                if ((lane & 3) == 0)
                    atomicAdd(&g_L[z * SEQ + rbase + i * 16 + h * 8], s);
            }
        return;
    }

#pragma unroll
    for (int i = 0; i < 2; i++) {
#pragma unroll
        for (int h = 0; h < 2; h++) {
            const int r = rbase + i * 16 + h * 8;
            const float linv = LSCALE ? (1.0f / g_L[z * SEQ + r]) : 1.0f;
#pragma unroll
            for (int j = 0; j < 8; j++) {
                const int c = cbase + j * 8;
                float v0 = acc[i][j][h * 2 + 0] * alpha;
                float v1 = acc[i][j][h * 2 + 1] * alpha;
                if (LSCALE) { v0 *= linv; v1 *= linv; }
                if (BIAS) { v0 += bias[c]; v1 += bias[c + 1]; }
                if (OUT_MODE == 0) {
                    float* C = cext + (long long)z * sC;
                    *(float2*)(C + (long long)r * ldC + c) = make_float2(v0, v1);
                } else {
                    bf16 h0, l0, h1, l1;
                    split2(v0, h0, l0);
                    split2(v1, h1, l1);
                    bf16* H = bbuf(tagOut)     + (long long)z * sC;
                    bf16* L = bbuf(tagOut + 1) + (long long)z * sC;
                    const long long idx = (long long)r * ldC + c;
                    *(uint32_t*)(H + idx) = pack2(h0, h1);
                    *(uint32_t*)(L + idx) = pack2(l0, l1);
                }
            }
        }
    }
}

// ---------------------------------------------------------------------------
// Fused prep kernel: block ranges dispatch all independent preprocessing.
//   [0,4096)        RoPE table (reference-matching fp32 pipeline)
//   [+32)           zero g_L
//   [+1024)         b2[n] = sum_c bv[c]*Wo[c,n]  (one block per n, reduction)
//   [+8192)         X -> hi/lo split
//   [+1024)         Wv -> hi/lo split (plain)
//   [+3072)         Wq/Wk/Wo -> transposed hi/lo split
// ---------------------------------------------------------------------------
#define NB_ROPE 4096
#define NB_ZERO 32
#define NB_B2   1024
#define NB_SX   8192
#define NB_SWV  1024
#define NB_WT   3072
#define NB_PREP (NB_ROPE + NB_ZERO + NB_B2 + NB_SX + NB_SWV + NB_WT)

__global__ void __launch_bounds__(256)
prep_kernel(const float* __restrict__ x,
            const float* __restrict__ Wq, const float* __restrict__ Wk,
            const float* __restrict__ Wv, const float* __restrict__ Wo,
            const float* __restrict__ bv) {
    __shared__ float tile[32][33];
    int blk = blockIdx.x;
    const int tid = threadIdx.x;

    if (blk < NB_ROPE) {               // RoPE table (4096*256 == SEQ*CH/2 exactly)
        const int idx = blk * 256 + tid;
        const int half = CH >> 1;
        const int t = idx / half, p = idx - t * half;
        float inv = 1.0f / powf(10000.0f, (float)(2 * p) / (float)CH);
        float s, c;
        sincosf((float)t * inv, &s, &c);
        g_ROPE[idx] = make_float2(c, s);
        return;
    }
    blk -= NB_ROPE;

    if (blk < NB_ZERO) {               // zero g_L (32*256 == MTOT)
        g_L[blk * 256 + tid] = 0.0f;
        return;
    }
    blk -= NB_ZERO;

    if (blk < NB_B2) {                 // b2[n], block per n, 256-thread reduce
        const int n = blk;
        float s = 0.0f;
        for (int c = tid; c < CH; c += 256)
            s += bv[c] * Wo[(long long)c * CH + n];
#pragma unroll
        for (int o = 16; o > 0; o >>= 1) s += __shfl_xor_sync(0xffffffffu, s, o);
        if ((tid & 31) == 0) tile[0][tid >> 5] = s;
        __syncthreads();
        if (tid == 0) {
            float v = 0.0f;
#pragma unroll
            for (int w = 0; w < 8; w++) v += tile[0][w];
            g_B2[n] = v;
        }
        return;
    }
    blk -= NB_B2;

    if (blk < NB_SX) {                 // X split (8192*256 == MTOT*CH/4)
        const int i = blk * 256 + tid;
        float4 xv = ((const float4*)x)[i];
        bf16 h[4], l[4];
        split2(xv.x, h[0], l[0]); split2(xv.y, h[1], l[1]);
        split2(xv.z, h[2], l[2]); split2(xv.w, h[3], l[3]);
        *(uint2*)(g_XH + (long long)i * 4) = *(const uint2*)h;
        *(uint2*)(g_XL + (long long)i * 4) = *(const uint2*)l;
        return;
    }
    blk -= NB_SX;

    if (blk < NB_SWV) {                // plain Wv split (1024*256 == CH*CH/4)
        const int i = blk * 256 + tid;
        float4 xv = ((const float4*)Wv)[i];
        bf16 h[4], l[4];
        split2(xv.x, h[0], l[0]); split2(xv.y, h[1], l[1]);
        split2(xv.z, h[2], l[2]); split2(xv.w, h[3], l[3]);
        *(uint2*)(g_WVH + (long long)i * 4) = *(const uint2*)h;
        *(uint2*)(g_WVL + (long long)i * 4) = *(const uint2*)l;
        return;
    }
    blk -= NB_SWV;

    {                                  // W^T splits: z = 0/1/2 -> Wq/Wk/Wo
        const int z = blk >> 10, rem = blk & 1023;
        const int bx = rem & 31, by = rem >> 5;
        const float* W = (z == 0) ? Wq : (z == 1) ? Wk : Wo;
        bf16* H = (z == 0) ? g_WQH : (z == 1) ? g_WKH : g_WOH;
        bf16* L = (z == 0) ? g_WQL : (z == 1) ? g_WKL : g_WOL;
        const int n0 = bx * 32, k0 = by * 32;
        const int tx = tid & 31, ty = tid >> 5;     // 32 x 8
#pragma unroll
        for (int i = 0; i < 32; i += 8)
            tile[ty + i][tx] = W[(long long)(k0 + ty + i) * CH + n0 + tx];
        __syncthreads();
#pragma unroll
        for (int i = 0; i < 32; i += 8) {
            bf16 h, l;
            split2(tile[tx][ty + i], h, l);
            const long long idx = (long long)(n0 + ty + i) * CH + k0 + tx;
            H[idx] = h;
            L[idx] = l;
        }
    }
}

// ---------------------------------------------------------------------------
// Launch
// ---------------------------------------------------------------------------
extern "C" void kernel_launch(void* const* d_in, const int* in_sizes, int n_in,
                              void* d_out, int out_size) {
    const float* x  = (const float*)d_in[0];
    const float* Wq = (const float*)d_in[1];
    const float* bq = (const float*)d_in[2];
    const float* Wk = (const float*)d_in[3];
    const float* bk = (const float*)d_in[4];
    const float* Wv = (const float*)d_in[5];
    const float* bv = (const float*)d_in[6];
    const float* Wo = (const float*)d_in[7];
    const float* bo = (const float*)d_in[8];
    float* out = (float*)d_out;

    const long long TC = (long long)SEQ * CH;
    const long long TT = (long long)SEQ * SEQ;

    cudaFuncSetAttribute(qkv_kernel,
                         cudaFuncAttributeMaxDynamicSharedMemorySize, SMEM_TOT);
    cudaFuncSetAttribute(hmma_gemm<1, false, false, false, false, false>,
                         cudaFuncAttributeMaxDynamicSharedMemorySize, SMEM_TOT);
    cudaFuncSetAttribute(hmma_gemm<2, false, true,  false, false, false>,
                         cudaFuncAttributeMaxDynamicSharedMemorySize, SMEM_TOT);
    cudaFuncSetAttribute(hmma_gemm<0, true,  false, true,  true,  true>,
                         cudaFuncAttributeMaxDynamicSharedMemorySize, SMEM_TOT);

    dim3 blk(256);

    // Fused prep (RoPE table, zero-L, b2, X split, Wv split, W^T splits)
    prep_kernel<<<NB_PREP, blk>>>(x, Wq, Wk, Wv, Wo, bv);

    // W2^T[n',k'] = sum_c Wo[c,n']*Wv[k',c]:  A = Wo^T, B = plain Wv
    dim3 gw2(CH / 128, CH / 128, 1);
    hmma_gemm<1, false, false, false, false, false><<<gw2, blk, SMEM_TOT>>>(
        TB_WOH, TB_WVH, CH, CH, 0, 0, nullptr, nullptr, CH, 0, TB_W2H, CH, 1.0f);

    // Fused projections: Q (RoPE), K (RoPE), VW = X·W2 + b2 (transposed)
    dim3 gqkv(CH / 128, MTOT / 128, 3);
    qkv_kernel<<<gqkv, blk, SMEM_TOT>>>(bq, bk);

    // Scores: exp(Q K^T / 32) causal-masked -> PH/PL hi/lo, row sums -> g_L
    const int nb = SEQ / 128;
    dim3 gsc(nb * (nb + 1) / 2, 1, BATCH);
    hmma_gemm<2, false, true, false, false, false><<<gsc, blk, SMEM_TOT>>>(
        TB_QH, TB_KH, CH, CH, TC, TC, nullptr, nullptr, SEQ, TT, 0, CH, 1.0f / 32.0f);

    // Final: out = (exp(S) · VW)/l + bo  (K-limited, LPT order)
    dim3 gpv(CH / 128, SEQ / 128, BATCH);
    hmma_gemm<0, true, false, true, true, true><<<gpv, blk, SMEM_TOT>>>(
        TB_PH, TB_VWH, SEQ, SEQ, TT, (long long)CH * SEQ, bo, out,
        CH, TC, 0, SEQ, 1.0f);
}